// round 17
// baseline (speedup 1.0000x reference)
#include <cuda_runtime.h>
#include <cuda_fp16.h>
#include <math.h>
#include <stdint.h>

#define BT 4096   // b*t
#define T  2048
#define E  1024
#define H  16
#define S  64

// Scratch (allocation-free rule: device globals), all fp16
__device__ __half g_X16[BT * E];
__device__ __half g_Q16[BT * E];
__device__ __half g_K16[BT * E];
__device__ __half g_V16[BT * E];
__device__ __half g_O16[BT * E];
__device__ __half g_Wq16[E * E];
__device__ __half g_Wk16[E * E];
__device__ __half g_Wv16[E * E];
__device__ __half g_Wu16[E * E];

// ---------------------------------------------------------------------------
// helpers
// ---------------------------------------------------------------------------
__device__ __forceinline__ unsigned smem_u32(const void* p) {
    return (unsigned)__cvta_generic_to_shared(p);
}
__device__ __forceinline__ void ldsm_x4(unsigned& r0, unsigned& r1,
                                        unsigned& r2, unsigned& r3, unsigned a) {
    asm volatile("ldmatrix.sync.aligned.m8n8.x4.shared.b16 {%0,%1,%2,%3}, [%4];"
                 : "=r"(r0), "=r"(r1), "=r"(r2), "=r"(r3) : "r"(a));
}
__device__ __forceinline__ void ldsm_x4t(unsigned& r0, unsigned& r1,
                                         unsigned& r2, unsigned& r3, unsigned a) {
    asm volatile("ldmatrix.sync.aligned.m8n8.x4.trans.shared.b16 {%0,%1,%2,%3}, [%4];"
                 : "=r"(r0), "=r"(r1), "=r"(r2), "=r"(r3) : "r"(a));
}
// fp16 mma: m16n8k16, fp32 accum
__device__ __forceinline__ void mma_f16(float* c, const unsigned* a, const unsigned* b) {
    asm volatile("mma.sync.aligned.m16n8k16.row.col.f32.f16.f16.f32 "
                 "{%0,%1,%2,%3}, {%4,%5,%6,%7}, {%8,%9}, {%0,%1,%2,%3};"
                 : "+f"(c[0]), "+f"(c[1]), "+f"(c[2]), "+f"(c[3])
                 : "r"(a[0]), "r"(a[1]), "r"(a[2]), "r"(a[3]),
                   "r"(b[0]), "r"(b[1]));
}
#define CP_ASYNC16(dst, src) \
    asm volatile("cp.async.cg.shared.global [%0], [%1], 16;" :: "r"(dst), "l"(src))
#define CP_COMMIT() asm volatile("cp.async.commit_group;")
#define CP_WAIT(n)  asm volatile("cp.async.wait_group %0;" :: "n"(n))

// ---------------------------------------------------------------------------
// fp32 -> fp16: all five tensors in ONE launch (range dispatch)
// chunks of 8: x = 524288 chunks, each W = 131072 chunks, total 1048576
// ---------------------------------------------------------------------------
__global__ __launch_bounds__(256) void cvt_all(const float* __restrict__ x,
                                               const float* __restrict__ wq,
                                               const float* __restrict__ wk,
                                               const float* __restrict__ wv,
                                               const float* __restrict__ wu,
                                               __half* __restrict__ gx,
                                               __half* __restrict__ gwq,
                                               __half* __restrict__ gwk,
                                               __half* __restrict__ gwv,
                                               __half* __restrict__ gwu)
{
    int i = blockIdx.x * blockDim.x + threadIdx.x;
    const float* src; __half* dst; int off;
    if (i < 524288) { src = x; dst = gx; off = i; }
    else {
        int j = i - 524288;
        int sel = j >> 17;
        off = j & 131071;
        if      (sel == 0) { src = wq; dst = gwq; }
        else if (sel == 1) { src = wk; dst = gwk; }
        else if (sel == 2) { src = wv; dst = gwv; }
        else               { src = wu; dst = gwu; }
    }
    float4 a = ((const float4*)src)[2 * off];
    float4 b = ((const float4*)src)[2 * off + 1];
    __half2 h[4];
    h[0] = __floats2half2_rn(a.x, a.y);
    h[1] = __floats2half2_rn(a.z, a.w);
    h[2] = __floats2half2_rn(b.x, b.y);
    h[3] = __floats2half2_rn(b.z, b.w);
    *(uint4*)(dst + (size_t)8 * off) = *(uint4*)h;
}

// ---------------------------------------------------------------------------
// GEMM core constants (identical layout to R15-passing kernel)
// ---------------------------------------------------------------------------
#define STG_B (128 * 80)            // bytes per tile per stage (10240)
#define NSTG 3
#define NK 32                       // 1024 / 32

// ---------------------------------------------------------------------------
// Fused QKV GEMM + per-head LayerNorm (z = blockIdx.z: 0=Q(+LN), 1=K(+LN), 2=V)
// C[M,N] = A[M,K]*B[N,K]^T, fp16 in/out, fp32 accum; LN over 64-col heads
// applied on fp32 accumulators in the epilogue.
// ---------------------------------------------------------------------------
__global__ __launch_bounds__(256) void gemm_qkv(const __half* __restrict__ A,
                                                const __half* __restrict__ Bq,
                                                const __half* __restrict__ Bk,
                                                const __half* __restrict__ Bv,
                                                __half* __restrict__ Cq,
                                                __half* __restrict__ Ck,
                                                __half* __restrict__ Cvv,
                                                const float* __restrict__ qlnw,
                                                const float* __restrict__ qlnb,
                                                const float* __restrict__ klnw,
                                                const float* __restrict__ klnb)
{
    extern __shared__ __align__(16) char smg[];
    const unsigned sA = smem_u32(smg);
    const unsigned sB = sA + NSTG * STG_B;

    const int z = blockIdx.z;
    const __half* B = (z == 0) ? Bq : (z == 1) ? Bk : Bv;
    __half* C16     = (z == 0) ? Cq : (z == 1) ? Ck : Cvv;

    const int tid  = threadIdx.x;
    const int lane = tid & 31;
    const int warp = tid >> 5;
    const int wm = (warp & 1) * 64;
    const int wn = (warp >> 1) * 32;
    const int bm = blockIdx.y * 128;
    const int bn = blockIdx.x * 128;

    float c[4][4][4];
#pragma unroll
    for (int mt = 0; mt < 4; mt++)
#pragma unroll
        for (int nt = 0; nt < 4; nt++)
#pragma unroll
            for (int i = 0; i < 4; i++) c[mt][nt][i] = 0.f;

    const int r0 = tid >> 2, c0 = tid & 3;
    const int r1 = (tid + 256) >> 2;
    const unsigned ad0 = sA + (unsigned)(r0 * 80 + c0 * 16);
    const unsigned ad1 = sA + (unsigned)(r1 * 80 + c0 * 16);
    const unsigned bd0 = sB + (unsigned)(r0 * 80 + c0 * 16);
    const unsigned bd1 = sB + (unsigned)(r1 * 80 + c0 * 16);
    const __half* as0 = A + (size_t)(bm + r0) * 1024 + c0 * 8;
    const __half* as1 = A + (size_t)(bm + r1) * 1024 + c0 * 8;
    const __half* bs0 = B + (size_t)(bn + r0) * 1024 + c0 * 8;
    const __half* bs1 = B + (size_t)(bn + r1) * 1024 + c0 * 8;

    auto issue = [&](int cs) {
        const unsigned so = (unsigned)((cs % NSTG) * STG_B);
        const int ko = cs * 32;
        CP_ASYNC16(ad0 + so, as0 + ko);
        CP_ASYNC16(ad1 + so, as1 + ko);
        CP_ASYNC16(bd0 + so, bs0 + ko);
        CP_ASYNC16(bd1 + so, bs1 + ko);
        CP_COMMIT();
    };

    issue(0);
    issue(1);

    const unsigned a_base0 = sA + (unsigned)((wm + (lane & 15)) * 80
                                             + ((lane >> 4) & 1) * 16);
    const unsigned b_base0 = sB + (unsigned)((wn + (lane & 7) + ((lane >> 4) & 1) * 8) * 80
                                             + ((lane >> 3) & 1) * 16);

    for (int i = 0; i < NK; i++) {
        if (i == NK - 1) { CP_WAIT(0); } else { CP_WAIT(1); }
        __syncthreads();
        if (i + 2 < NK) issue(i + 2);

        const unsigned so = (unsigned)((i % NSTG) * STG_B);
        const unsigned a_base = a_base0 + so;
        const unsigned b_base = b_base0 + so;
#pragma unroll
        for (int ks = 0; ks < 2; ks++) {
            unsigned af[4][4], bf[4][2];
#pragma unroll
            for (int mt = 0; mt < 4; mt++)
                ldsm_x4(af[mt][0], af[mt][1], af[mt][2], af[mt][3],
                        a_base + (unsigned)(mt * 16 * 80 + ks * 32));
#pragma unroll
            for (int p = 0; p < 2; p++)
                ldsm_x4(bf[2 * p][0], bf[2 * p][1], bf[2 * p + 1][0], bf[2 * p + 1][1],
                        b_base + (unsigned)(p * 16 * 80 + ks * 32));
#pragma unroll
            for (int mt = 0; mt < 4; mt++)
#pragma unroll
                for (int nt = 0; nt < 4; nt++)
                    mma_f16(c[mt][nt], af[mt], bf[nt]);
        }
    }

    if (z == 2) {
        // V: plain fp16 store
#pragma unroll
        for (int mt = 0; mt < 4; mt++)
#pragma unroll
            for (int nt = 0; nt < 4; nt++) {
                int row = bm + wm + mt * 16 + (lane >> 2);
                int col = bn + wn + nt * 8 + (lane & 3) * 2;
                *(__half2*)&C16[(size_t)row * 1024 + col] =
                    __floats2half2_rn(c[mt][nt][0], c[mt][nt][1]);
                *(__half2*)&C16[(size_t)(row + 8) * 1024 + col] =
                    __floats2half2_rn(c[mt][nt][2], c[mt][nt][3]);
            }
        return;
    }

    // ---- fused LayerNorm epilogue (Q or K) ----
    // Tile cols [bn, bn+128) = heads 2*bx, 2*bx+1 (64 cols each).
    // head = warp>>2 (column group), chalf = (warp>>1)&1 (which 32-col half).
    float* part = (float*)smg;   // 4KB, aliases dead cp.async buffers
    __syncthreads();             // all warps done with mainloop smem
    const int head  = warp >> 2;
    const int chalf = (warp >> 1) & 1;
    const int row0  = lane >> 2;
    const int colb  = 2 * (lane & 3);

#pragma unroll
    for (int mt = 0; mt < 4; mt++) {
#pragma unroll
        for (int hh = 0; hh < 2; hh++) {
            float s1 = 0.f, s2 = 0.f;
#pragma unroll
            for (int nt = 0; nt < 4; nt++) {
                float v0 = c[mt][nt][2 * hh], v1 = c[mt][nt][2 * hh + 1];
                s1 += v0 + v1;
                s2 += v0 * v0 + v1 * v1;
            }
            s1 += __shfl_xor_sync(0xffffffffu, s1, 1);
            s2 += __shfl_xor_sync(0xffffffffu, s2, 1);
            s1 += __shfl_xor_sync(0xffffffffu, s1, 2);
            s2 += __shfl_xor_sync(0xffffffffu, s2, 2);
            if ((lane & 3) == 0) {
                int row = wm + mt * 16 + row0 + 8 * hh;
                int idx = ((head * 128 + row) * 2 + chalf) * 2;
                part[idx]     = s1;
                part[idx + 1] = s2;
            }
        }
    }
    __syncthreads();

    const float* lw = (z == 0) ? qlnw : klnw;
    const float* lb = (z == 0) ? qlnb : klnb;
    float wv8[8], bv8[8];
#pragma unroll
    for (int nt = 0; nt < 4; nt++)
#pragma unroll
        for (int e = 0; e < 2; e++) {
            int cl = (wn + nt * 8 + colb + e) & 63;
            wv8[nt * 2 + e] = lw[cl];
            bv8[nt * 2 + e] = lb[cl];
        }

#pragma unroll
    for (int mt = 0; mt < 4; mt++) {
#pragma unroll
        for (int hh = 0; hh < 2; hh++) {
            int row = wm + mt * 16 + row0 + 8 * hh;
            int idx = (head * 128 + row) * 4;
            float sum = part[idx]     + part[idx + 2];
            float ssq = part[idx + 1] + part[idx + 3];
            float mu  = sum * (1.0f / 64.0f);
            float var = ssq * (1.0f / 64.0f) - mu * mu;
            float rs  = rsqrtf(var + 1e-5f);
            __half* crow = C16 + (size_t)(bm + row) * 1024 + bn;
#pragma unroll
            for (int nt = 0; nt < 4; nt++) {
                float v0 = (c[mt][nt][2 * hh]     - mu) * rs * wv8[nt * 2]     + bv8[nt * 2];
                float v1 = (c[mt][nt][2 * hh + 1] - mu) * rs * wv8[nt * 2 + 1] + bv8[nt * 2 + 1];
                *(__half2*)&crow[wn + nt * 8 + colb] = __floats2half2_rn(v0, v1);
            }
        }
    }
}

// ---------------------------------------------------------------------------
// Final projection GEMM: fp16 in, fp32 out (unchanged mainloop from R15)
// ---------------------------------------------------------------------------
__global__ __launch_bounds__(256) void gemm_out(const __half* __restrict__ A,
                                                const __half* __restrict__ B,
                                                float* __restrict__ Cf)
{
    extern __shared__ __align__(16) char smg[];
    const unsigned sA = smem_u32(smg);
    const unsigned sB = sA + NSTG * STG_B;

    const int tid  = threadIdx.x;
    const int lane = tid & 31;
    const int warp = tid >> 5;
    const int wm = (warp & 1) * 64;
    const int wn = (warp >> 1) * 32;
    const int bm = blockIdx.y * 128;
    const int bn = blockIdx.x * 128;

    float c[4][4][4];
#pragma unroll
    for (int mt = 0; mt < 4; mt++)
#pragma unroll
        for (int nt = 0; nt < 4; nt++)
#pragma unroll
            for (int i = 0; i < 4; i++) c[mt][nt][i] = 0.f;

    const int r0 = tid >> 2, c0 = tid & 3;
    const int r1 = (tid + 256) >> 2;
    const unsigned ad0 = sA + (unsigned)(r0 * 80 + c0 * 16);
    const unsigned ad1 = sA + (unsigned)(r1 * 80 + c0 * 16);
    const unsigned bd0 = sB + (unsigned)(r0 * 80 + c0 * 16);
    const unsigned bd1 = sB + (unsigned)(r1 * 80 + c0 * 16);
    const __half* as0 = A + (size_t)(bm + r0) * 1024 + c0 * 8;
    const __half* as1 = A + (size_t)(bm + r1) * 1024 + c0 * 8;
    const __half* bs0 = B + (size_t)(bn + r0) * 1024 + c0 * 8;
    const __half* bs1 = B + (size_t)(bn + r1) * 1024 + c0 * 8;

    auto issue = [&](int cs) {
        const unsigned so = (unsigned)((cs % NSTG) * STG_B);
        const int ko = cs * 32;
        CP_ASYNC16(ad0 + so, as0 + ko);
        CP_ASYNC16(ad1 + so, as1 + ko);
        CP_ASYNC16(bd0 + so, bs0 + ko);
        CP_ASYNC16(bd1 + so, bs1 + ko);
        CP_COMMIT();
    };

    issue(0);
    issue(1);

    const unsigned a_base0 = sA + (unsigned)((wm + (lane & 15)) * 80
                                             + ((lane >> 4) & 1) * 16);
    const unsigned b_base0 = sB + (unsigned)((wn + (lane & 7) + ((lane >> 4) & 1) * 8) * 80
                                             + ((lane >> 3) & 1) * 16);

    for (int i = 0; i < NK; i++) {
        if (i == NK - 1) { CP_WAIT(0); } else { CP_WAIT(1); }
        __syncthreads();
        if (i + 2 < NK) issue(i + 2);

        const unsigned so = (unsigned)((i % NSTG) * STG_B);
        const unsigned a_base = a_base0 + so;
        const unsigned b_base = b_base0 + so;
#pragma unroll
        for (int ks = 0; ks < 2; ks++) {
            unsigned af[4][4], bf[4][2];
#pragma unroll
            for (int mt = 0; mt < 4; mt++)
                ldsm_x4(af[mt][0], af[mt][1], af[mt][2], af[mt][3],
                        a_base + (unsigned)(mt * 16 * 80 + ks * 32));
#pragma unroll
            for (int p = 0; p < 2; p++)
                ldsm_x4(bf[2 * p][0], bf[2 * p][1], bf[2 * p + 1][0], bf[2 * p + 1][1],
                        b_base + (unsigned)(p * 16 * 80 + ks * 32));
#pragma unroll
            for (int mt = 0; mt < 4; mt++)
#pragma unroll
                for (int nt = 0; nt < 4; nt++)
                    mma_f16(c[mt][nt], af[mt], bf[nt]);
        }
    }

#pragma unroll
    for (int mt = 0; mt < 4; mt++)
#pragma unroll
        for (int nt = 0; nt < 4; nt++) {
            int row = bm + wm + mt * 16 + (lane >> 2);
            int col = bn + wn + nt * 8 + (lane & 3) * 2;
            *(float2*)&Cf[(size_t)row * 1024 + col] =
                make_float2(c[mt][nt][0], c[mt][nt][1]);
            *(float2*)&Cf[(size_t)(row + 8) * 1024 + col] =
                make_float2(c[mt][nt][2], c[mt][nt][3]);
        }
}

// ---------------------------------------------------------------------------
// Causal flash attention, fp16 mma.sync m16n8k16 (unchanged from R15-passing).
// ---------------------------------------------------------------------------
#define ALD 72
#define AROW 144
#define AQP_OFF 0
#define AK_OFF  9216
#define AV_OFF  27648
#define ATT_SMEM 46080

__global__ __launch_bounds__(128) void attn(const __half* __restrict__ Q,
                                            const __half* __restrict__ K,
                                            const __half* __restrict__ V,
                                            __half* __restrict__ O)
{
    extern __shared__ __align__(16) char sma[];
    const unsigned sbase = smem_u32(sma);
    __half* QP = (__half*)sma;

    const int qt = gridDim.x - 1 - blockIdx.x;
    const int bh = blockIdx.y;
    const int b  = bh >> 4, h = bh & 15;
    const int tid  = threadIdx.x;
    const int lane = tid & 31;
    const int w    = tid >> 5;

    const size_t qbase = ((size_t)b * T + (size_t)qt * 64) * E + h * S;

    for (int idx = tid; idx < 512; idx += 128) {
        int r = idx >> 3, c = idx & 7;
        *(uint4*)(QP + r * ALD + c * 8) = *(const uint4*)(Q + qbase + (size_t)r * E + c * 8);
    }

    auto issueKV = [&](int kt, int sb) {
        const size_t kb = ((size_t)b * T + (size_t)kt * 64) * E + h * S;
        const __half* kp = K + kb;
        const __half* vp = V + kb;
        const unsigned kd = sbase + AK_OFF + (unsigned)sb * 9216;
        const unsigned vd = sbase + AV_OFF + (unsigned)sb * 9216;
#pragma unroll
        for (int i = 0; i < 4; i++) {
            int idx = i * 128 + tid;
            int r = idx >> 3, c = idx & 7;
            CP_ASYNC16(kd + r * AROW + c * 16, kp + (size_t)r * E + c * 8);
            CP_ASYNC16(vd + r * AROW + c * 16, vp + (size_t)r * E + c * 8);
        }
        CP_COMMIT();
    };

    issueKV(0, 0);
    __syncthreads();

    const unsigned a_base = sbase + AQP_OFF +
        (unsigned)((16 * w + (lane & 15)) * AROW + ((lane >> 4) & 1) * 16);
    unsigned Qf[4][4];
#pragma unroll
    for (int ks = 0; ks < 4; ks++)
        ldsm_x4(Qf[ks][0], Qf[ks][1], Qf[ks][2], Qf[ks][3],
                a_base + (unsigned)(ks * 32));

    const unsigned kb_off = (unsigned)(((lane & 7) + ((lane >> 4) & 1) * 8) * AROW
                                       + ((lane >> 3) & 1) * 16);
    const unsigned vb_off = (unsigned)(((lane & 7) + ((lane >> 3) & 1) * 8) * AROW
                                       + ((lane >> 4) & 1) * 16);

    float o[8][4];
    float m[2], l[2];
#pragma unroll
    for (int nt = 0; nt < 8; nt++)
#pragma unroll
        for (int i = 0; i < 4; i++) o[nt][i] = 0.f;
    m[0] = m[1] = -1e30f;
    l[0] = l[1] = 0.f;

    const int row0 = (lane >> 2);
    const int colb = 2 * (lane & 3);

    for (int kt = 0; kt <= qt; kt++) {
        const int sb = kt & 1;
        CP_WAIT(0);
        __syncthreads();
        if (kt < qt) issueKV(kt + 1, sb ^ 1);

        const unsigned kbb = sbase + AK_OFF + (unsigned)sb * 9216 + kb_off;
        const unsigned vbb = sbase + AV_OFF + (unsigned)sb * 9216 + vb_off;

        float s[8][4];
#pragma unroll
        for (int nt = 0; nt < 8; nt++)
#pragma unroll
            for (int i = 0; i < 4; i++) s[nt][i] = 0.f;

#pragma unroll
        for (int ks = 0; ks < 4; ks++) {
            unsigned bf[8][2];
#pragma unroll
            for (int p = 0; p < 4; p++)
                ldsm_x4(bf[2 * p][0], bf[2 * p][1], bf[2 * p + 1][0], bf[2 * p + 1][1],
                        kbb + (unsigned)(p * 16 * AROW + ks * 32));
#pragma unroll
            for (int nt = 0; nt < 8; nt++)
                mma_f16(s[nt], Qf[ks], bf[nt]);
        }

        const bool diag = (kt == qt);
#pragma unroll
        for (int hh = 0; hh < 2; hh++) {
            const int rloc = 16 * w + row0 + 8 * hh;
            float rmax = -1e30f;
#pragma unroll
            for (int nt = 0; nt < 8; nt++) {
#pragma unroll
                for (int e = 0; e < 2; e++) {
                    float sv = s[nt][2 * hh + e] * 0.125f;
                    if (diag && (8 * nt + colb + e > rloc)) sv = -1e30f;
                    s[nt][2 * hh + e] = sv;
                    rmax = fmaxf(rmax, sv);
                }
            }
            rmax = fmaxf(rmax, __shfl_xor_sync(0xffffffffu, rmax, 1));
            rmax = fmaxf(rmax, __shfl_xor_sync(0xffffffffu, rmax, 2));
            float mnew = fmaxf(m[hh], rmax);
            float alpha = __expf(m[hh] - mnew);
            m[hh] = mnew;
            float rsum = 0.f;
#pragma unroll
            for (int nt = 0; nt < 8; nt++) {
#pragma unroll
                for (int e = 0; e < 2; e++) {
                    float p = __expf(s[nt][2 * hh + e] - mnew);
                    s[nt][2 * hh + e] = p;
                    rsum += p;
                }
            }
            rsum += __shfl_xor_sync(0xffffffffu, rsum, 1);
            rsum += __shfl_xor_sync(0xffffffffu, rsum, 2);
            l[hh] = l[hh] * alpha + rsum;
#pragma unroll
            for (int nt = 0; nt < 8; nt++) {
                o[nt][2 * hh]     *= alpha;
                o[nt][2 * hh + 1] *= alpha;
            }
        }

        __syncwarp();
#pragma unroll
        for (int nt = 0; nt < 8; nt++) {
            *(__half2*)&QP[(16 * w + row0) * ALD + 8 * nt + colb] =
                __floats2half2_rn(s[nt][0], s[nt][1]);
            *(__half2*)&QP[(16 * w + row0 + 8) * ALD + 8 * nt + colb] =
                __floats2half2_rn(s[nt][2], s[nt][3]);
        }
        __syncwarp();

#pragma unroll
        for (int ks = 0; ks < 4; ks++) {
            unsigned pa[4];
            ldsm_x4(pa[0], pa[1], pa[2], pa[3], a_base + (unsigned)(ks * 32));
            unsigned bv[8][2];
#pragma unroll
            for (int p = 0; p < 4; p++)
                ldsm_x4t(bv[2 * p][0], bv[2 * p][1], bv[2 * p + 1][0], bv[2 * p + 1][1],
                         vbb + (unsigned)(ks * 16 * AROW + p * 32));
#pragma unroll
            for (int nt = 0; nt < 8; nt++)
                mma_f16(o[nt], pa, bv[nt]);
        }
    }

    const float inv0 = 1.0f / l[0];
    const float inv1 = 1.0f / l[1];
    const size_t r0g = qbase + (size_t)(16 * w + row0) * E;
    const size_t r1g = qbase + (size_t)(16 * w + row0 + 8) * E;
#pragma unroll
    for (int nt = 0; nt < 8; nt++) {
        int col = 8 * nt + colb;
        *(__half2*)&O[r0g + col] = __floats2half2_rn(o[nt][0] * inv0, o[nt][1] * inv0);
        *(__half2*)&O[r1g + col] = __floats2half2_rn(o[nt][2] * inv1, o[nt][3] * inv1);
    }
}

// ---------------------------------------------------------------------------
extern "C" void kernel_launch(void* const* d_in, const int* in_sizes, int n_in,
                              void* d_out, int out_size)
{
    const float* x    = (const float*)d_in[0];
    const float* Wk   = (const float*)d_in[1];
    const float* Wq   = (const float*)d_in[2];
    const float* Wv   = (const float*)d_in[3];
    const float* Wu   = (const float*)d_in[4];
    const float* klnw = (const float*)d_in[5];
    const float* klnb = (const float*)d_in[6];
    const float* qlnw = (const float*)d_in[7];
    const float* qlnb = (const float*)d_in[8];
    float* out = (float*)d_out;

    __half *gx, *gq, *gk, *gv, *go, *gwq, *gwk, *gwv, *gwu;
    cudaGetSymbolAddress((void**)&gx,  g_X16);
    cudaGetSymbolAddress((void**)&gq,  g_Q16);
    cudaGetSymbolAddress((void**)&gk,  g_K16);
    cudaGetSymbolAddress((void**)&gv,  g_V16);
    cudaGetSymbolAddress((void**)&go,  g_O16);
    cudaGetSymbolAddress((void**)&gwq, g_Wq16);
    cudaGetSymbolAddress((void**)&gwk, g_Wk16);
    cudaGetSymbolAddress((void**)&gwv, g_Wv16);
    cudaGetSymbolAddress((void**)&gwu, g_Wu16);

    const int gemm_smem = 2 * NSTG * STG_B;   // 61440
    cudaFuncSetAttribute(gemm_qkv, cudaFuncAttributeMaxDynamicSharedMemorySize, gemm_smem);
    cudaFuncSetAttribute(gemm_out, cudaFuncAttributeMaxDynamicSharedMemorySize, gemm_smem);
    cudaFuncSetAttribute(attn, cudaFuncAttributeMaxDynamicSharedMemorySize, ATT_SMEM);

    cvt_all<<<4096, 256>>>(x, Wq, Wk, Wv, Wu, gx, gwq, gwk, gwv, gwu);

    gemm_qkv<<<dim3(8, 32, 3), 256, gemm_smem>>>(gx, gwq, gwk, gwv, gq, gk, gv,
                                                 qlnw, qlnb, klnw, klnb);

    attn<<<dim3(32, 32), 128, ATT_SMEM>>>(gq, gk, gv, go);

    gemm_out<<<dim3(8, 32), 256, gemm_smem>>>(go, gwu, out);
}